// round 1
// baseline (speedup 1.0000x reference)
#include <cuda_runtime.h>
#include <math.h>

#define BATCH 16
#define TQ 4
#define DMODEL 2048
#define NH 8
#define NG 4
#define GSZ 2
#define HD 256
#define KVBLK 16
#define WINDOW 1024
#define NBLK 257
#define NTOK 64          // BATCH*TQ
#define NFQKV 4096       // 2048 q + 1024 k + 1024 v
#define NSPLIT 4         // attention KV splits
#define NKSPL 8          // GEMM split-K

// ---------------- scratch (device globals; no allocation allowed) ----------
__device__ float g_part_qkv[NKSPL][NTOK][NFQKV];        // 8 MB
__device__ float g_q[NTOK][NH][HD];
__device__ float g_k[NTOK][NG][HD];
__device__ float g_v[NTOK][NG][HD];
__device__ float g_cos[NTOK][HD / 2];
__device__ float g_sin[NTOK][HD / 2];
__device__ float g_pacc[BATCH * NG * 8 * NSPLIT][HD];   // 2 MB
__device__ float g_pm[BATCH * NG * 8 * NSPLIT];
__device__ float g_pl[BATCH * NG * 8 * NSPLIT];
__device__ float g_obuf[NTOK][DMODEL];
__device__ float g_part_out[NKSPL][NTOK][DMODEL];       // 4 MB

// ---------------- generic 64-token split-K GEMM ----------------------------
// C_part[ks][tok][f] = sum_{k in chunk ks} A[tok][k] * Wrow(f)[k]
// Wrow(f): f<n0 -> W0 row f ; f<n0+n1 -> W1 row f-n0 ; else W2 row f-n0-n1.
// All W row strides are DMODEL (2048). Tile: 64 tokens x 64 feats, K chunk 256.
__device__ __forceinline__ void gemm_body(
    const float* __restrict__ A,
    const float* __restrict__ W0, int n0,
    const float* __restrict__ W1, int n1,
    const float* __restrict__ W2,
    float* __restrict__ part, int NF)
{
    const int ft = blockIdx.x;
    const int ks = blockIdx.y;
    const int tid = threadIdx.x;
    const int tx = tid & 15, ty = tid >> 4;
    const int fbase = ft * 64;
    const int kbase = ks * 256;

    __shared__ float Xs[16][64];
    __shared__ float Ws[16][64];

    float c[4][4] = {};

    const int lrow = tid >> 2;        // 0..63
    const int lk4 = (tid & 3) * 4;    // 0,4,8,12

    const int f = fbase + lrow;
    const float* wrow;
    if (f < n0)            wrow = W0 + (size_t)f * DMODEL;
    else if (f < n0 + n1)  wrow = W1 + (size_t)(f - n0) * DMODEL;
    else                   wrow = W2 + (size_t)(f - n0 - n1) * DMODEL;
    const float* arow = A + (size_t)lrow * DMODEL;

    for (int kt = 0; kt < 256; kt += 16) {
        float4 xa = *(const float4*)(arow + kbase + kt + lk4);
        float4 wa = *(const float4*)(wrow + kbase + kt + lk4);
        __syncthreads();
        Xs[lk4 + 0][lrow] = xa.x; Xs[lk4 + 1][lrow] = xa.y;
        Xs[lk4 + 2][lrow] = xa.z; Xs[lk4 + 3][lrow] = xa.w;
        Ws[lk4 + 0][lrow] = wa.x; Ws[lk4 + 1][lrow] = wa.y;
        Ws[lk4 + 2][lrow] = wa.z; Ws[lk4 + 3][lrow] = wa.w;
        __syncthreads();
#pragma unroll
        for (int kk = 0; kk < 16; kk++) {
            float a0 = Xs[kk][ty * 4 + 0];
            float a1 = Xs[kk][ty * 4 + 1];
            float a2 = Xs[kk][ty * 4 + 2];
            float a3 = Xs[kk][ty * 4 + 3];
            float4 bv = *(const float4*)&Ws[kk][tx * 4];
            c[0][0] += a0 * bv.x; c[0][1] += a0 * bv.y; c[0][2] += a0 * bv.z; c[0][3] += a0 * bv.w;
            c[1][0] += a1 * bv.x; c[1][1] += a1 * bv.y; c[1][2] += a1 * bv.z; c[1][3] += a1 * bv.w;
            c[2][0] += a2 * bv.x; c[2][1] += a2 * bv.y; c[2][2] += a2 * bv.z; c[2][3] += a2 * bv.w;
            c[3][0] += a3 * bv.x; c[3][1] += a3 * bv.y; c[3][2] += a3 * bv.z; c[3][3] += a3 * bv.w;
        }
    }
#pragma unroll
    for (int i = 0; i < 4; i++) {
        float4 v = make_float4(c[i][0], c[i][1], c[i][2], c[i][3]);
        *(float4*)&part[((size_t)ks * NTOK + (ty * 4 + i)) * NF + fbase + tx * 4] = v;
    }
}

__global__ void k_gemm_qkv(const float* __restrict__ x,
                           const float* __restrict__ Wq,
                           const float* __restrict__ Wk,
                           const float* __restrict__ Wv)
{
    gemm_body(x, Wq, 2048, Wk, 1024, Wv, &g_part_qkv[0][0][0], NFQKV);
}

__global__ void k_gemm_o(const float* __restrict__ Wo)
{
    gemm_body(&g_obuf[0][0], Wo, 2048, Wo, 0, Wo, &g_part_out[0][0][0], DMODEL);
}

// ---------------- RoPE table (fp64 accuracy, computed once per launch) -----
__global__ void k_rope_table(const int* __restrict__ kv_lens)
{
    int idx = blockIdx.x * blockDim.x + threadIdx.x;   // 64*128
    if (idx >= NTOK * 128) return;
    int bt = idx >> 7, j = idx & 127;
    int b = bt >> 2, t = bt & 3;
    int pos = kv_lens[b] + t;
    double inv = exp(-((double)j / 128.0) * log(10000.0));
    double ang = (double)pos * inv;
    double sd, cd;
    sincos(ang, &sd, &cd);
    g_cos[bt][j] = (float)cd;
    g_sin[bt][j] = (float)sd;
}

// ---------------- split-K reduce + RMSNorm + RoPE + store q/k/v ------------
// grid: (NTOK, 16): u<8 q-head u ; u<12 k-group u-8 ; else v-group u-12.
__global__ void k_normrope(const float* __restrict__ q_scale,
                           const float* __restrict__ k_scale)
{
    const int bt = blockIdx.x;
    const int u = blockIdx.y;
    const int d = threadIdx.x;      // 0..255

    int f;
    if (u < 8)       f = u * HD + d;
    else if (u < 12) f = 2048 + (u - 8) * HD + d;
    else             f = 3072 + (u - 12) * HD + d;

    float v = 0.f;
#pragma unroll
    for (int s = 0; s < NKSPL; s++) v += g_part_qkv[s][bt][f];

    if (u >= 12) { g_v[bt][u - 12][d] = v; return; }

    __shared__ float red[256];
    __shared__ float sx[256];
    red[d] = v * v;
    __syncthreads();
    for (int s = 128; s > 0; s >>= 1) {
        if (d < s) red[d] += red[d + s];
        __syncthreads();
    }
    float rn = rsqrtf(red[0] / (float)HD + 1e-6f);
    float sc = (u < 8) ? q_scale[d] : k_scale[d];
    sx[d] = v * rn * (1.f + sc);
    __syncthreads();

    int j = d & 127;
    float c = g_cos[bt][j], s = g_sin[bt][j];
    float x1 = sx[j], x2 = sx[j + 128];
    float out = (d < 128) ? (x1 * c - x2 * s) : (x2 * c + x1 * s);

    if (u < 8) g_q[bt][u][d] = out;
    else       g_k[bt][u - 8][d] = out;
}

// ---------------- flash-decode attention with KV split ---------------------
// grid: (BATCH*NG, NSPLIT), 256 threads. Warp w handles query qi=w
// (qi = gi*4 + t; head h = g*2+gi). Fresh keys (kpos >= kv_len) come from
// g_k/g_v scratch; cache is never modified.
__global__ void k_attn(const float* __restrict__ k_blocks,
                       const float* __restrict__ v_blocks,
                       const int* __restrict__ block_tables,
                       const int* __restrict__ kv_lens)
{
    const int bg = blockIdx.x;
    const int b = bg >> 2, g = bg & 3;
    const int sp = blockIdx.y;
    const int tid = threadIdx.x;
    const int warp = tid >> 5, lane = tid & 31;

    const int kvl = kv_lens[b];
    const int lo = max(0, kvl - (WINDOW - 1));
    const int hi = kvl + 3;
    const int L = hi - lo + 1;
    const int chunk = (L + NSPLIT - 1) / NSPLIT;
    const int kstart = lo + sp * chunk;
    const int kend = min(kstart + chunk, hi + 1);

    __shared__ float Qs[8][HD];
    __shared__ float Ks[16][HD];
    __shared__ float Vs[16][HD];
    __shared__ const float* rpK[16];
    __shared__ const float* rpV[16];

    for (int i = tid; i < 8 * 64; i += 256) {
        int qi = i >> 6;
        int d4 = (i & 63) * 4;
        int gi = qi >> 2, t = qi & 3;
        *(float4*)&Qs[qi][d4] =
            *(const float4*)&g_q[b * TQ + t][g * GSZ + gi][d4];
    }

    const int qi = warp;
    const int t = qi & 3;
    const int post = kvl + t;
    const int lot = post - (WINDOW - 1);

    float m = -INFINITY, l = 0.f;
    float acc[8] = {0.f, 0.f, 0.f, 0.f, 0.f, 0.f, 0.f, 0.f};

    for (int k0 = kstart; k0 < kend; k0 += 16) {
        const int nk = min(16, kend - k0);
        __syncthreads();                 // everyone done with previous tile
        if (tid < 16) {
            int kpos = k0 + tid;
            const float* kp = &g_k[0][0][0];
            const float* vp = &g_v[0][0][0];
            if (tid < nk) {
                if (kpos < kvl) {
                    int blk = block_tables[b * NBLK + (kpos >> 4)];
                    size_t off = (((size_t)blk * NG + g) * KVBLK + (kpos & 15)) * HD;
                    kp = k_blocks + off;
                    vp = v_blocks + off;
                } else {
                    int tf = kpos - kvl;
                    kp = &g_k[b * TQ + tf][g][0];
                    vp = &g_v[b * TQ + tf][g][0];
                }
            }
            rpK[tid] = kp;
            rpV[tid] = vp;
        }
        __syncthreads();
        for (int i = tid; i < 16 * 64; i += 256) {
            int kk = i >> 6;
            int d4 = (i & 63) * 4;
            *(float4*)&Ks[kk][d4] = *(const float4*)(rpK[kk] + d4);
            *(float4*)&Vs[kk][d4] = *(const float4*)(rpV[kk] + d4);
        }
        __syncthreads();

        for (int kk = 0; kk < nk; kk++) {
            int kpos = k0 + kk;
            if (kpos > post || kpos < lot) continue;   // uniform per warp
            float s = 0.f;
#pragma unroll
            for (int i = 0; i < 8; i++)
                s += Qs[qi][lane + 32 * i] * Ks[kk][lane + 32 * i];
#pragma unroll
            for (int o = 16; o; o >>= 1) s += __shfl_xor_sync(0xffffffffu, s, o);
            s *= 0.0625f;   // 256^-0.5
            float mn = fmaxf(m, s);
            float co = __expf(m - mn);     // m=-inf -> 0
            float p = __expf(s - mn);
            l = l * co + p;
#pragma unroll
            for (int i = 0; i < 8; i++)
                acc[i] = acc[i] * co + p * Vs[kk][lane + 32 * i];
            m = mn;
        }
    }

    const int pi = (bg * 8 + qi) * NSPLIT + sp;
    if (lane == 0) { g_pm[pi] = m; g_pl[pi] = l; }
#pragma unroll
    for (int i = 0; i < 8; i++) g_pacc[pi][lane + 32 * i] = acc[i];
}

// ---------------- combine partial softmax ----------------------------------
__global__ void k_combine()
{
    const int qidx = blockIdx.x;   // 512
    const int d = threadIdx.x;

    float M = -INFINITY;
#pragma unroll
    for (int s = 0; s < NSPLIT; s++) M = fmaxf(M, g_pm[qidx * NSPLIT + s]);
    float Lt = 0.f, od = 0.f;
#pragma unroll
    for (int s = 0; s < NSPLIT; s++) {
        float ms = g_pm[qidx * NSPLIT + s];
        float w = (ms == -INFINITY) ? 0.f : __expf(ms - M);
        Lt += g_pl[qidx * NSPLIT + s] * w;
        od += g_pacc[qidx * NSPLIT + s][d] * w;
    }
    float o = od / Lt;

    int t = qidx & 3;
    int gi = (qidx >> 2) & 1;
    int g = (qidx >> 3) & 3;
    int b = qidx >> 5;
    g_obuf[b * TQ + t][(g * GSZ + gi) * HD + d] = o;
}

// ---------------- final split-K reduce to output ---------------------------
__global__ void k_reduce_out(float* __restrict__ out)
{
    int idx = blockIdx.x * blockDim.x + threadIdx.x;   // 64*2048
    if (idx >= NTOK * DMODEL) return;
    int bt = idx / DMODEL, dc = idx % DMODEL;
    float v = 0.f;
#pragma unroll
    for (int s = 0; s < NKSPL; s++) v += g_part_out[s][bt][dc];
    out[idx] = v;
}

// ---------------------------------------------------------------------------
extern "C" void kernel_launch(void* const* d_in, const int* in_sizes, int n_in,
                              void* d_out, int out_size)
{
    const float* x   = (const float*)d_in[0];
    const float* Wq  = (const float*)d_in[1];
    const float* Wk  = (const float*)d_in[2];
    const float* Wv  = (const float*)d_in[3];
    const float* Wo  = (const float*)d_in[4];
    const float* qns = (const float*)d_in[5];
    const float* kns = (const float*)d_in[6];
    const float* kb  = (const float*)d_in[7];
    const float* vb  = (const float*)d_in[8];
    const int* btab  = (const int*)d_in[9];
    const int* kvl   = (const int*)d_in[10];
    float* out = (float*)d_out;

    k_gemm_qkv<<<dim3(NFQKV / 64, NKSPL), 256>>>(x, Wq, Wk, Wv);
    k_rope_table<<<(NTOK * 128 + 255) / 256, 256>>>(kvl);
    k_normrope<<<dim3(NTOK, 16), 256>>>(qns, kns);
    k_attn<<<dim3(BATCH * NG, NSPLIT), 256>>>(kb, vb, btab, kvl);
    k_combine<<<BATCH * NG * 8, 256>>>();
    k_gemm_o<<<dim3(DMODEL / 64, NKSPL), 256>>>(Wo);
    k_reduce_out<<<(NTOK * DMODEL + 255) / 256, 256>>>(out);
}

// round 2
// speedup vs baseline: 1.4473x; 1.4473x over previous
#include <cuda_runtime.h>
#include <math.h>

#define BATCH 16
#define TQ 4
#define DMODEL 2048
#define NH 8
#define NG 4
#define GSZ 2
#define HD 256
#define KVBLK 16
#define WINDOW 1024
#define NBLK 257
#define NTOK 64          // BATCH*TQ
#define NFQKV 4096       // 2048 q + 1024 k + 1024 v
#define NSPLIT 8         // attention KV splits
#define NKSPL 8          // GEMM split-K

// ---------------- scratch (device globals; no allocation allowed) ----------
__device__ float g_part_qkv[NKSPL][NTOK][NFQKV];        // 8 MB
__device__ float g_q[NTOK][NH][HD];
__device__ float g_k[NTOK][NG][HD];
__device__ float g_v[NTOK][NG][HD];
__device__ float g_cos[NTOK][HD / 2];
__device__ float g_sin[NTOK][HD / 2];
__device__ float g_pacc[BATCH * NG * 8 * NSPLIT][HD];   // 4 MB
__device__ float g_pm[BATCH * NG * 8 * NSPLIT];
__device__ float g_pl[BATCH * NG * 8 * NSPLIT];
__device__ float g_obuf[NTOK][DMODEL];
__device__ float g_part_out[NKSPL][NTOK][DMODEL];       // 4 MB

// ---------------- generic 64-token split-K GEMM ----------------------------
__device__ __forceinline__ void gemm_body(
    const float* __restrict__ A,
    const float* __restrict__ W0, int n0,
    const float* __restrict__ W1, int n1,
    const float* __restrict__ W2,
    float* __restrict__ part, int NF)
{
    const int ft = blockIdx.x;
    const int ks = blockIdx.y;
    const int tid = threadIdx.x;
    const int tx = tid & 15, ty = tid >> 4;
    const int fbase = ft * 64;
    const int kbase = ks * 256;

    __shared__ float Xs[16][64];
    __shared__ float Ws[16][64];

    float c[4][4] = {};

    const int lrow = tid >> 2;        // 0..63
    const int lk4 = (tid & 3) * 4;    // 0,4,8,12

    const int f = fbase + lrow;
    const float* wrow;
    if (f < n0)            wrow = W0 + (size_t)f * DMODEL;
    else if (f < n0 + n1)  wrow = W1 + (size_t)(f - n0) * DMODEL;
    else                   wrow = W2 + (size_t)(f - n0 - n1) * DMODEL;
    const float* arow = A + (size_t)lrow * DMODEL;

    for (int kt = 0; kt < 256; kt += 16) {
        float4 xa = *(const float4*)(arow + kbase + kt + lk4);
        float4 wa = *(const float4*)(wrow + kbase + kt + lk4);
        __syncthreads();
        Xs[lk4 + 0][lrow] = xa.x; Xs[lk4 + 1][lrow] = xa.y;
        Xs[lk4 + 2][lrow] = xa.z; Xs[lk4 + 3][lrow] = xa.w;
        Ws[lk4 + 0][lrow] = wa.x; Ws[lk4 + 1][lrow] = wa.y;
        Ws[lk4 + 2][lrow] = wa.z; Ws[lk4 + 3][lrow] = wa.w;
        __syncthreads();
#pragma unroll
        for (int kk = 0; kk < 16; kk++) {
            float a0 = Xs[kk][ty * 4 + 0];
            float a1 = Xs[kk][ty * 4 + 1];
            float a2 = Xs[kk][ty * 4 + 2];
            float a3 = Xs[kk][ty * 4 + 3];
            float4 bv = *(const float4*)&Ws[kk][tx * 4];
            c[0][0] += a0 * bv.x; c[0][1] += a0 * bv.y; c[0][2] += a0 * bv.z; c[0][3] += a0 * bv.w;
            c[1][0] += a1 * bv.x; c[1][1] += a1 * bv.y; c[1][2] += a1 * bv.z; c[1][3] += a1 * bv.w;
            c[2][0] += a2 * bv.x; c[2][1] += a2 * bv.y; c[2][2] += a2 * bv.z; c[2][3] += a2 * bv.w;
            c[3][0] += a3 * bv.x; c[3][1] += a3 * bv.y; c[3][2] += a3 * bv.z; c[3][3] += a3 * bv.w;
        }
    }
#pragma unroll
    for (int i = 0; i < 4; i++) {
        float4 v = make_float4(c[i][0], c[i][1], c[i][2], c[i][3]);
        *(float4*)&part[((size_t)ks * NTOK + (ty * 4 + i)) * NF + fbase + tx * 4] = v;
    }
}

__global__ void k_gemm_qkv(const float* __restrict__ x,
                           const float* __restrict__ Wq,
                           const float* __restrict__ Wk,
                           const float* __restrict__ Wv)
{
    gemm_body(x, Wq, 2048, Wk, 1024, Wv, &g_part_qkv[0][0][0], NFQKV);
}

__global__ void k_gemm_o(const float* __restrict__ Wo)
{
    gemm_body(&g_obuf[0][0], Wo, 2048, Wo, 0, Wo, &g_part_out[0][0][0], DMODEL);
}

// ---------------- RoPE table (fp64 accuracy) --------------------------------
__global__ void k_rope_table(const int* __restrict__ kv_lens)
{
    int idx = blockIdx.x * blockDim.x + threadIdx.x;   // 64*128
    if (idx >= NTOK * 128) return;
    int bt = idx >> 7, j = idx & 127;
    int b = bt >> 2, t = bt & 3;
    int pos = kv_lens[b] + t;
    double inv = exp(-((double)j / 128.0) * log(10000.0));
    double ang = (double)pos * inv;
    double sd, cd;
    sincos(ang, &sd, &cd);
    g_cos[bt][j] = (float)cd;
    g_sin[bt][j] = (float)sd;
}

// ---------------- split-K reduce + RMSNorm + RoPE + store q/k/v ------------
__global__ void k_normrope(const float* __restrict__ q_scale,
                           const float* __restrict__ k_scale)
{
    const int bt = blockIdx.x;
    const int u = blockIdx.y;
    const int d = threadIdx.x;      // 0..255

    int f;
    if (u < 8)       f = u * HD + d;
    else if (u < 12) f = 2048 + (u - 8) * HD + d;
    else             f = 3072 + (u - 12) * HD + d;

    float v = 0.f;
#pragma unroll
    for (int s = 0; s < NKSPL; s++) v += g_part_qkv[s][bt][f];

    if (u >= 12) { g_v[bt][u - 12][d] = v; return; }

    __shared__ float red[256];
    __shared__ float sx[256];
    red[d] = v * v;
    __syncthreads();
    for (int s = 128; s > 0; s >>= 1) {
        if (d < s) red[d] += red[d + s];
        __syncthreads();
    }
    float rn = rsqrtf(red[0] / (float)HD + 1e-6f);
    float sc = (u < 8) ? q_scale[d] : k_scale[d];
    sx[d] = v * rn * (1.f + sc);
    __syncthreads();

    int j = d & 127;
    float c = g_cos[bt][j], s = g_sin[bt][j];
    float x1 = sx[j], x2 = sx[j + 128];
    float out = (d < 128) ? (x1 * c - x2 * s) : (x2 * c + x1 * s);

    if (u < 8) g_q[bt][u][d] = out;
    else       g_k[bt][u - 8][d] = out;
}

// ---------------- flash-decode attention, tile-batched softmax -------------
// grid: (BATCH*NG, NSPLIT), 256 threads. Warp w = query qi (gi*4+t).
// Per 16-key tile: all 16 scores computed with independent shuffle-reduce
// chains (ILP), single tile-max, single accumulator rescale, then PV pass.
__global__ void __launch_bounds__(256)
k_attn(const float* __restrict__ k_blocks,
       const float* __restrict__ v_blocks,
       const int* __restrict__ block_tables,
       const int* __restrict__ kv_lens)
{
    const int bg = blockIdx.x;
    const int b = bg >> 2, g = bg & 3;
    const int sp = blockIdx.y;
    const int tid = threadIdx.x;
    const int warp = tid >> 5, lane = tid & 31;

    const int kvl = kv_lens[b];
    const int lo = max(0, kvl - (WINDOW - 1));
    const int hi = kvl + 3;
    const int L = hi - lo + 1;
    const int chunk = (L + NSPLIT - 1) / NSPLIT;
    const int kstart = lo + sp * chunk;
    const int kend = min(kstart + chunk, hi + 1);

    __shared__ float Ks[16][HD];
    __shared__ float Vs[16][HD];
    __shared__ const float* rpK[16];
    __shared__ const float* rpV[16];

    // preload this warp's query into registers (2 x float4 per lane)
    const int qi = warp;
    const int gi = qi >> 2, t = qi & 3;
    float4 q1 = *(const float4*)&g_q[b * TQ + t][g * GSZ + gi][lane * 4];
    float4 q2 = *(const float4*)&g_q[b * TQ + t][g * GSZ + gi][128 + lane * 4];

    const int post = kvl + t;
    const int lot = post - (WINDOW - 1);

    float m = -INFINITY, l = 0.f;
    float4 acc1 = {0.f, 0.f, 0.f, 0.f};
    float4 acc2 = {0.f, 0.f, 0.f, 0.f};

    for (int k0 = kstart; k0 < kend; k0 += 16) {
        const int nk = min(16, kend - k0);
        __syncthreads();
        if (tid < 16) {
            int kpos = k0 + tid;
            const float* kp = &g_k[0][0][0];
            const float* vp = &g_v[0][0][0];
            if (tid < nk) {
                if (kpos < kvl) {
                    int blk = block_tables[b * NBLK + (kpos >> 4)];
                    size_t off = (((size_t)blk * NG + g) * KVBLK + (kpos & 15)) * HD;
                    kp = k_blocks + off;
                    vp = v_blocks + off;
                } else {
                    int tf = kpos - kvl;
                    kp = &g_k[b * TQ + tf][g][0];
                    vp = &g_v[b * TQ + tf][g][0];
                }
            }
            rpK[tid] = kp;
            rpV[tid] = vp;
        }
        __syncthreads();
        for (int i = tid; i < 16 * 64; i += 256) {
            int kk = i >> 6;
            int d4 = (i & 63) * 4;
            *(float4*)&Ks[kk][d4] = *(const float4*)(rpK[kk] + d4);
            *(float4*)&Vs[kk][d4] = *(const float4*)(rpV[kk] + d4);
        }
        __syncthreads();

        // ---- phase 1: 16 scores, independent reduce chains ----
        float s[16];
#pragma unroll
        for (int kk = 0; kk < 16; kk++) {
            float4 kv1 = *(const float4*)&Ks[kk][lane * 4];
            float4 kv2 = *(const float4*)&Ks[kk][128 + lane * 4];
            float d = q1.x * kv1.x + q1.y * kv1.y + q1.z * kv1.z + q1.w * kv1.w
                    + q2.x * kv2.x + q2.y * kv2.y + q2.z * kv2.z + q2.w * kv2.w;
#pragma unroll
            for (int o = 16; o; o >>= 1) d += __shfl_xor_sync(0xffffffffu, d, o);
            int kpos = k0 + kk;
            s[kk] = (kk < nk && kpos <= post && kpos >= lot)
                        ? d * 0.0625f : -INFINITY;
        }

        // ---- phase 2: tile max (register tree) ----
        float smax = s[0];
#pragma unroll
        for (int kk = 1; kk < 16; kk++) smax = fmaxf(smax, s[kk]);

        if (smax != -INFINITY) {
            float mn = fmaxf(m, smax);
            float co = __expf(m - mn);          // m=-inf -> 0
            l *= co;
            acc1.x *= co; acc1.y *= co; acc1.z *= co; acc1.w *= co;
            acc2.x *= co; acc2.y *= co; acc2.z *= co; acc2.w *= co;
            m = mn;

            // ---- phase 3: PV accumulation ----
#pragma unroll
            for (int kk = 0; kk < 16; kk++) {
                float p = __expf(s[kk] - mn);   // masked -> 0
                l += p;
                float4 v1 = *(const float4*)&Vs[kk][lane * 4];
                float4 v2 = *(const float4*)&Vs[kk][128 + lane * 4];
                acc1.x += p * v1.x; acc1.y += p * v1.y;
                acc1.z += p * v1.z; acc1.w += p * v1.w;
                acc2.x += p * v2.x; acc2.y += p * v2.y;
                acc2.z += p * v2.z; acc2.w += p * v2.w;
            }
        }
    }

    const int pi = (bg * 8 + qi) * NSPLIT + sp;
    if (lane == 0) { g_pm[pi] = m; g_pl[pi] = l; }
    *(float4*)&g_pacc[pi][lane * 4] = acc1;
    *(float4*)&g_pacc[pi][128 + lane * 4] = acc2;
}

// ---------------- combine partial softmax ----------------------------------
__global__ void k_combine()
{
    const int qidx = blockIdx.x;   // 512
    const int d = threadIdx.x;

    float M = -INFINITY;
#pragma unroll
    for (int s = 0; s < NSPLIT; s++) M = fmaxf(M, g_pm[qidx * NSPLIT + s]);
    float Lt = 0.f, od = 0.f;
#pragma unroll
    for (int s = 0; s < NSPLIT; s++) {
        float ms = g_pm[qidx * NSPLIT + s];
        float w = (ms == -INFINITY) ? 0.f : __expf(ms - M);
        Lt += g_pl[qidx * NSPLIT + s] * w;
        od += g_pacc[qidx * NSPLIT + s][d] * w;
    }
    float o = od / Lt;

    int t = qidx & 3;
    int gi = (qidx >> 2) & 1;
    int g = (qidx >> 3) & 3;
    int b = qidx >> 5;
    g_obuf[b * TQ + t][(g * GSZ + gi) * HD + d] = o;
}

// ---------------- final split-K reduce to output ---------------------------
__global__ void k_reduce_out(float* __restrict__ out)
{
    int idx = blockIdx.x * blockDim.x + threadIdx.x;   // 64*2048
    if (idx >= NTOK * DMODEL) return;
    int bt = idx / DMODEL, dc = idx % DMODEL;
    float v = 0.f;
#pragma unroll
    for (int s = 0; s < NKSPL; s++) v += g_part_out[s][bt][dc];
    out[idx] = v;
}

// ---------------------------------------------------------------------------
extern "C" void kernel_launch(void* const* d_in, const int* in_sizes, int n_in,
                              void* d_out, int out_size)
{
    const float* x   = (const float*)d_in[0];
    const float* Wq  = (const float*)d_in[1];
    const float* Wk  = (const float*)d_in[2];
    const float* Wv  = (const float*)d_in[3];
    const float* Wo  = (const float*)d_in[4];
    const float* qns = (const float*)d_in[5];
    const float* kns = (const float*)d_in[6];
    const float* kb  = (const float*)d_in[7];
    const float* vb  = (const float*)d_in[8];
    const int* btab  = (const int*)d_in[9];
    const int* kvl   = (const int*)d_in[10];
    float* out = (float*)d_out;

    k_gemm_qkv<<<dim3(NFQKV / 64, NKSPL), 256>>>(x, Wq, Wk, Wv);
    k_rope_table<<<(NTOK * 128 + 255) / 256, 256>>>(kvl);
    k_normrope<<<dim3(NTOK, 16), 256>>>(qns, kns);
    k_attn<<<dim3(BATCH * NG, NSPLIT), 256>>>(kb, vb, btab, kvl);
    k_combine<<<BATCH * NG * 8, 256>>>();
    k_gemm_o<<<dim3(DMODEL / 64, NKSPL), 256>>>(Wo);
    k_reduce_out<<<(NTOK * DMODEL + 255) / 256, 256>>>(out);
}